// round 4
// baseline (speedup 1.0000x reference)
#include <cuda_runtime.h>
#include <math.h>
#include <stdint.h>

#define NMAXT 3329      // 1024 query + 1 sep + 2304 max prompts (logical)
#define NPAD  3344      // token-dim padding (multiple of 16)
#define SLD   3344      // score-matrix row stride
#define GPTS  2304
#define NBATCH 4

// ---------------- static device scratch (zero-initialized, never freed) ---------
__device__ int   g_M[NBATCH];
__device__ int   g_rows[NBATCH*GPTS];
__device__ int   g_cols[NBATCH*GPTS];
__device__ float g_X   [(size_t)NBATCH*NPAD*1024];
__device__ float g_Y   [(size_t)NBATCH*NPAD*1024];
__device__ float g_QKV [(size_t)NBATCH*NPAD*3072];   // pad rows stay 0 (V zeros)
__device__ float g_S   [(size_t)NBATCH*4*NPAD*SLD];  // pad cols stay 0
__device__ float g_Hbuf[(size_t)NBATCH*NPAD*4096];
__device__ float g_Qpe [1024*1024];
__device__ float g_Ppe [(size_t)NBATCH*GPTS*1024];
__device__ float g_Hp  [(size_t)NBATCH*GPTS*512];
__device__ float g_Pft [(size_t)NBATCH*GPTS*1024];

__device__ __forceinline__ float geluf(float x) {
    return 0.5f * x * (1.0f + erff(x * 0.7071067811865475f));
}
__device__ __forceinline__ float tf32r(float x) {
    float r; asm("cvt.rna.tf32.f32 %0, %1;" : "=f"(r) : "f"(x)); return r;
}
__device__ __forceinline__ float warpSum(float v) {
    #pragma unroll
    for (int o = 16; o; o >>= 1) v += __shfl_xor_sync(0xFFFFFFFFu, v, o);
    return v;
}
__device__ __forceinline__ float warpMax(float v) {
    #pragma unroll
    for (int o = 16; o; o >>= 1) v = fmaxf(v, __shfl_xor_sync(0xFFFFFFFFu, v, o));
    return v;
}

// ---------------- mask compaction (row-major order == np.nonzero) ---------------
__global__ void compact_k(const int* __restrict__ mask) {
    int b = threadIdx.x;
    if (b >= NBATCH) return;
    const int* mb = mask + b * GPTS;
    int cnt = 0;
    for (int i = 0; i < GPTS; i++) {
        if (mb[i] > 0) {
            g_rows[b*GPTS + cnt] = i / 48;
            g_cols[b*GPTS + cnt] = i % 48;
            cnt++;
        }
    }
    g_M[b] = cnt;
}

// ---------------- query positional encoding -------------------------------------
__global__ void qpe_k(const float* __restrict__ gauss) {
    int t = blockIdx.x;            // t = i*32 + j
    int i = t >> 5, j = t & 31;
    float cx = 2.0f * ((j + 0.5f) / 32.0f) - 1.0f;
    float cy = 2.0f * ((i + 0.5f) / 32.0f) - 1.0f;
    for (int k = threadIdx.x; k < 512; k += 256) {
        float ang = 6.283185307179586f * (cx * gauss[k] + cy * gauss[512 + k]);
        g_Qpe[(size_t)t*1024 + k]       = sinf(ang);
        g_Qpe[(size_t)t*1024 + 512 + k] = cosf(ang);
    }
}

// ------------- prompt PE + depth hidden layer gelu(d*w1+b1) ---------------------
__global__ void pembed_k(const float* __restrict__ depth, const float* __restrict__ gauss,
                         const float* __restrict__ w1, const float* __restrict__ b1) {
    int b = blockIdx.y, j = blockIdx.x;
    if (j >= g_M[b]) return;
    int r = g_rows[b*GPTS + j], c = g_cols[b*GPTS + j];
    float cx = 2.0f * ((c + 0.5f) / 48.0f) - 1.0f;
    float cy = 2.0f * ((r + 0.5f) / 48.0f) - 1.0f;
    float d = depth[b*GPTS + r*48 + c];
    size_t base = (size_t)b*GPTS + j;
    for (int k = threadIdx.x; k < 512; k += 256) {
        float ang = 6.283185307179586f * (cx * gauss[k] + cy * gauss[512 + k]);
        g_Ppe[base*1024 + k]       = sinf(ang);
        g_Ppe[base*1024 + 512 + k] = cosf(ang);
        g_Hp [base*512  + k]       = geluf(fmaf(d, w1[k], b1[k]));
    }
}

// ---------------- build residual stream -----------------------------------------
__global__ void build_x(const float* __restrict__ img, const float* __restrict__ sep0) {
    int b = blockIdx.y, t = blockIdx.x;
    if (t >= 1025 + g_M[b]) return;
    float* x = g_X + ((size_t)b*NPAD + t) * 1024;
    if (t < 1024) {
        const float* im = img + ((size_t)b*1024 + t) * 1024;
        for (int c = threadIdx.x; c < 1024; c += 256) x[c] = im[c] + g_Qpe[(size_t)t*1024 + c];
    } else if (t == 1024) {
        for (int c = threadIdx.x; c < 1024; c += 256) x[c] = sep0[c];
    } else {
        size_t base = (size_t)b*GPTS + (t - 1025);
        for (int c = threadIdx.x; c < 1024; c += 256)
            x[c] = g_Pft[base*1024 + c] + g_Ppe[base*1024 + c];
    }
}

__global__ void sep_rep(const float* __restrict__ sep1) {
    int b = blockIdx.x;
    float* x = g_X + ((size_t)b*NPAD + 1024) * 1024;
    for (int c = threadIdx.x; c < 1024; c += blockDim.x) x[c] = sep1[c];
}

// ---------------- layernorm -----------------------------------------------------
__global__ void ln_k(const float* __restrict__ Xin, float* __restrict__ Yout,
                     const float* __restrict__ w, const float* __restrict__ bb) {
    int b = blockIdx.y, t = blockIdx.x;
    if (t >= 1025 + g_M[b]) return;
    int tid = threadIdx.x;
    const float4* x4 = (const float4*)(Xin + ((size_t)b*NPAD + t) * 1024);
    float4 v = x4[tid];
    float s  = v.x + v.y + v.z + v.w;
    float sq = v.x*v.x + v.y*v.y + v.z*v.z + v.w*v.w;
    __shared__ float shs[8], shq[8], res[2];
    float ws = warpSum(s), wq = warpSum(sq);
    if ((tid & 31) == 0) { shs[tid>>5] = ws; shq[tid>>5] = wq; }
    __syncthreads();
    if (tid == 0) {
        float a = 0.f, q = 0.f;
        #pragma unroll
        for (int i = 0; i < 8; i++) { a += shs[i]; q += shq[i]; }
        res[0] = a; res[1] = q;
    }
    __syncthreads();
    float mean = res[0] * (1.0f/1024.0f);
    float var  = res[1] * (1.0f/1024.0f) - mean*mean;
    float rstd = rsqrtf(var + 1e-5f);
    float4 wv = ((const float4*)w)[tid];
    float4 bv = ((const float4*)bb)[tid];
    float4 o;
    o.x = (v.x - mean) * rstd * wv.x + bv.x;
    o.y = (v.y - mean) * rstd * wv.y + bv.y;
    o.z = (v.z - mean) * rstd * wv.z + bv.z;
    o.w = (v.w - mean) * rstd * wv.w + bv.w;
    ((float4*)(Yout + ((size_t)b*NPAD + t) * 1024))[tid] = o;
}

// ---------------- row softmax ----------------------------------------------------
__global__ void softmax_k() {
    int z = blockIdx.y;            // b*4 + head
    int b = z >> 2;
    int Nd = 1025 + g_M[b];
    int row = blockIdx.x;
    if (row >= Nd) return;
    float* s = g_S + (size_t)z*NPAD*SLD + (size_t)row*SLD;
    int tid = threadIdx.x;
    __shared__ float red[8];

    float m = -3.4e38f;
    for (int j = tid; j < Nd; j += 256) m = fmaxf(m, s[j]);
    m = warpMax(m);
    if ((tid & 31) == 0) red[tid>>5] = m;
    __syncthreads();
    if (tid == 0) {
        float v = red[0];
        #pragma unroll
        for (int i = 1; i < 8; i++) v = fmaxf(v, red[i]);
        red[0] = v;
    }
    __syncthreads();
    m = red[0];
    __syncthreads();

    float sum = 0.f;
    for (int j = tid; j < Nd; j += 256) { float e = expf(s[j] - m); s[j] = e; sum += e; }
    sum = warpSum(sum);
    if ((tid & 31) == 0) red[tid>>5] = sum;
    __syncthreads();
    if (tid == 0) {
        float v = 0.f;
        #pragma unroll
        for (int i = 0; i < 8; i++) v += red[i];
        red[0] = v;
    }
    __syncthreads();
    float inv = 1.0f / red[0];
    for (int j = tid; j < Nd; j += 256) s[j] *= inv;
}

// =========================== tf32 tensor-core GEMM ==============================
// C = alpha * A @ (TRANSB ? B^T : B) (+bias)(+gelu)(+=C)
// 128x128x16 CTA tile, 8 warps (2x4), 64x32 warp tile, m16n8k8 tf32 mma.
__device__ __forceinline__ int dimval(int st, int dyn, int b) {
    if (dyn == 1) return 1025 + g_M[b];
    if (dyn == 2) return g_M[b];
    return st;
}

#define MMA_TF32(d, a, bq)                                              \
    asm volatile("mma.sync.aligned.m16n8k8.row.col.f32.tf32.tf32.f32 "  \
        "{%0,%1,%2,%3},{%4,%5,%6,%7},{%8,%9},{%0,%1,%2,%3};"            \
        : "+f"(d[0]),"+f"(d[1]),"+f"(d[2]),"+f"(d[3])                   \
        : "r"(a[0]),"r"(a[1]),"r"(a[2]),"r"(a[3]),"r"(bq[0]),"r"(bq[1]))

template<bool TRANSB, int EPI, bool ACCUM>
__global__ void __launch_bounds__(256) gemm_tc(
    const float* __restrict__ A, long long aOut, long long aIn, int lda,
    const float* __restrict__ B, long long bOut, long long bIn, int ldb,
    float* __restrict__ C, long long cOut, long long cIn, int ldc,
    const float* __restrict__ bias,
    int nInner, int Mst, int Nst, int Kst,
    int dynM, int dynN, int dynK, float alpha)
{
    int z = blockIdx.z;
    int b = z / nInner, ii = z - b*nInner;
    int Mr = dimval(Mst, dynM, b);
    int Nc = dimval(Nst, dynN, b);
    int K  = dimval(Kst, dynK, b);
    int Kpad = (K + 15) & ~15;          // padding regions hold zeros by construction
    int m0 = blockIdx.y * 128, n0 = blockIdx.x * 128;
    if (m0 >= Mr || n0 >= Nc) return;
    A += b*aOut + ii*aIn;
    B += b*bOut + ii*bIn;
    C += b*cOut + ii*cIn;

    __shared__ float As[128][20];       // [m][k], pad 4: conflict-free frag reads
    __shared__ float Bs[16][136];       // [k][n], pad 8: conflict-free frag reads

    int tid  = threadIdx.x;
    int wid  = tid >> 5, lane = tid & 31;
    int wm   = (wid >> 2) * 64;
    int wn   = (wid & 3) * 32;
    int g    = lane >> 2, t4 = lane & 3;

    float acc[4][4][4];
    #pragma unroll
    for (int i = 0; i < 4; i++)
        #pragma unroll
        for (int j = 0; j < 4; j++)
            #pragma unroll
            for (int e = 0; e < 4; e++) acc[i][j][e] = 0.f;

    for (int k0 = 0; k0 < Kpad; k0 += 16) {
        // ---- load A tile (128x16) ----
        #pragma unroll
        for (int i = 0; i < 2; i++) {
            int idx = tid + 256*i;
            int r = idx >> 2, c4 = (idx & 3) << 2;
            float4 v = make_float4(0.f,0.f,0.f,0.f);
            int gm = m0 + r;
            if (gm < Mr) v = *(const float4*)(A + (long long)gm*lda + (k0 + c4));
            As[r][c4+0] = tf32r(v.x);
            As[r][c4+1] = tf32r(v.y);
            As[r][c4+2] = tf32r(v.z);
            As[r][c4+3] = tf32r(v.w);
        }
        // ---- load B tile (16x128) ----
        if (TRANSB) {
            #pragma unroll
            for (int i = 0; i < 2; i++) {
                int idx = tid + 256*i;
                int n = idx >> 2, k4 = (idx & 3) << 2;
                float4 v = make_float4(0.f,0.f,0.f,0.f);
                int gn = n0 + n;
                if (gn < Nc) v = *(const float4*)(B + (long long)gn*ldb + (k0 + k4));
                Bs[k4+0][n] = tf32r(v.x);
                Bs[k4+1][n] = tf32r(v.y);
                Bs[k4+2][n] = tf32r(v.z);
                Bs[k4+3][n] = tf32r(v.w);
            }
        } else {
            #pragma unroll
            for (int i = 0; i < 2; i++) {
                int idx = tid + 256*i;
                int r = idx >> 5, c4 = (idx & 31) << 2;
                int gn = n0 + c4;
                float4 v = make_float4(0.f,0.f,0.f,0.f);
                const float* Bp = B + (long long)(k0 + r)*ldb;
                if (gn + 3 < Nc) v = *(const float4*)(Bp + gn);
                else {
                    if (gn + 0 < Nc) v.x = Bp[gn+0];
                    if (gn + 1 < Nc) v.y = Bp[gn+1];
                    if (gn + 2 < Nc) v.z = Bp[gn+2];
                    if (gn + 3 < Nc) v.w = Bp[gn+3];
                }
                Bs[r][c4+0] = tf32r(v.x);
                Bs[r][c4+1] = tf32r(v.y);
                Bs[r][c4+2] = tf32r(v.z);
                Bs[r][c4+3] = tf32r(v.w);
            }
        }
        __syncthreads();

        // ---- 2 x k8 mma steps ----
        #pragma unroll
        for (int ks = 0; ks < 2; ks++) {
            int kk = ks * 8;
            uint32_t af[4][4], bf[4][2];
            #pragma unroll
            for (int mf = 0; mf < 4; mf++) {
                int r = wm + mf*16;
                af[mf][0] = __float_as_uint(As[r+g  ][kk+t4  ]);
                af[mf][1] = __float_as_uint(As[r+g+8][kk+t4  ]);
                af[mf][2] = __float_as_uint(As[r+g  ][kk+t4+4]);
                af[mf][3] = __float_as_uint(As[r+g+8][kk+t4+4]);
            }
            #pragma unroll
            for (int nf = 0; nf < 4; nf++) {
                int c = wn + nf*8;
                bf[nf][0] = __float_as_uint(Bs[kk+t4  ][c+g]);
                bf[nf][1] = __float_as_uint(Bs[kk+t4+4][c+g]);
            }
            #pragma unroll
            for (int mf = 0; mf < 4; mf++)
                #pragma unroll
                for (int nf = 0; nf < 4; nf++)
                    MMA_TF32(acc[mf][nf], af[mf], bf[nf]);
        }
        __syncthreads();
    }

    // ---- epilogue ----
    #pragma unroll
    for (int mf = 0; mf < 4; mf++) {
        #pragma unroll
        for (int nf = 0; nf < 4; nf++) {
            int gmA = m0 + wm + mf*16 + g;
            int gnA = n0 + wn + nf*8 + 2*t4;
            #pragma unroll
            for (int e = 0; e < 4; e++) {
                int gm = gmA + ((e >> 1) << 3);
                int gn = gnA + (e & 1);
                if (gm < Mr && gn < Nc) {
                    float v = acc[mf][nf][e] * alpha;
                    if (bias) v += bias[gn];
                    if (EPI == 1) v = geluf(v);
                    long long off = (long long)gm*ldc + gn;
                    if (ACCUM) C[off] += v;
                    else       C[off]  = v;
                }
            }
        }
    }
}

// ---------------- output ---------------------------------------------------------
__global__ void out_k(const float* __restrict__ img, float* __restrict__ out) {
    int b = blockIdx.y, t = blockIdx.x;
    const float* src = (g_M[b] == 0)
        ? img + ((size_t)b*1024 + t) * 1024
        : g_X + ((size_t)b*NPAD + t) * 1024;
    float* o = out + ((size_t)b*1024 + t) * 1024;
    for (int c = threadIdx.x; c < 1024; c += 256) o[c] = src[c];
}

// ================================ host ==========================================
extern "C" void kernel_launch(void* const* d_in, const int* in_sizes, int n_in,
                              void* d_out, int out_size) {
    const float* img   = (const float*)d_in[0];
    const float* depth = (const float*)d_in[1];
    const int*   mask  = (const int*)  d_in[2];
    const float* gauss = (const float*)d_in[5];
    const float* w1    = (const float*)d_in[6];
    const float* b1    = (const float*)d_in[7];
    const float* w2    = (const float*)d_in[8];
    const float* b2    = (const float*)d_in[9];
    const float* sep   = (const float*)d_in[10];
    const float* ln1w  = (const float*)d_in[11];
    const float* ln1b  = (const float*)d_in[12];
    const float* qkvw  = (const float*)d_in[13];
    const float* qkvb  = (const float*)d_in[14];
    const float* projw = (const float*)d_in[15];
    const float* projb = (const float*)d_in[16];
    const float* ln2w  = (const float*)d_in[17];
    const float* ln2b  = (const float*)d_in[18];
    const float* m1w   = (const float*)d_in[19];
    const float* m1b   = (const float*)d_in[20];
    const float* m2w   = (const float*)d_in[21];
    const float* m2b   = (const float*)d_in[22];
    float* out = (float*)d_out;

    float *pX, *pY, *pQKV, *pS, *pH, *pHp, *pPft;
    cudaGetSymbolAddress((void**)&pX,   g_X);
    cudaGetSymbolAddress((void**)&pY,   g_Y);
    cudaGetSymbolAddress((void**)&pQKV, g_QKV);
    cudaGetSymbolAddress((void**)&pS,   g_S);
    cudaGetSymbolAddress((void**)&pH,   g_Hbuf);
    cudaGetSymbolAddress((void**)&pHp,  g_Hp);
    cudaGetSymbolAddress((void**)&pPft, g_Pft);

    const long long SX   = (long long)NPAD * 1024;
    const long long SQKV = (long long)NPAD * 3072;
    const long long SH   = (long long)NPAD * 4096;
    const long long SS1  = (long long)NPAD * SLD;    // per head
    const long long SSB  = 4LL * SS1;                // per batch

    compact_k<<<1, NBATCH>>>(mask);
    qpe_k<<<1024, 256>>>(gauss);
    pembed_k<<<dim3(GPTS, NBATCH), 256>>>(depth, gauss, w1, b1);

    // prompt features: Pft = Hp @ w2 + b2   (rows = g_M[b])
    gemm_tc<false,0,false><<<dim3(8, 18, NBATCH), 256>>>(
        pHp, (long long)GPTS*512, 0, 512,
        w2, 0, 0, 1024,
        pPft, (long long)GPTS*1024, 0, 1024,
        b2, 1, 0, 1024, 512, 2, 0, 0, 1.0f);

    build_x<<<dim3(NMAXT, NBATCH), 256>>>(img, sep);

    for (int i = 0; i < 2; i++) {
        if (i) sep_rep<<<NBATCH, 256>>>(sep + (size_t)i*1024);

        ln_k<<<dim3(NMAXT, NBATCH), 256>>>(pX, pY, ln1w + i*1024, ln1b + i*1024);

        // QKV = Y @ qkv_w + qkv_b
        gemm_tc<false,0,false><<<dim3(24, 27, NBATCH), 256>>>(
            pY, SX, 0, 1024,
            qkvw + (size_t)i*1024*3072, 0, 0, 3072,
            pQKV, SQKV, 0, 3072,
            qkvb + (size_t)i*3072, 1, 0, 3072, 1024, 1, 0, 0, 1.0f);

        // S = Q K^T / 16   (per head, z = b*4+h)
        gemm_tc<true,0,false><<<dim3(27, 27, NBATCH*4), 256>>>(
            pQKV, SQKV, 256, 3072,
            pQKV + 1024, SQKV, 256, 3072,
            pS, SSB, SS1, SLD,
            nullptr, 4, 0, 0, 256, 1, 1, 0, 0.0625f);

        softmax_k<<<dim3(NMAXT, NBATCH*4), 256>>>();

        // O = S @ V  -> Y (per-head column slice)
        gemm_tc<false,0,false><<<dim3(2, 27, NBATCH*4), 256>>>(
            pS, SSB, SS1, SLD,
            pQKV + 2048, SQKV, 256, 3072,
            pY, SX, 256, 1024,
            nullptr, 4, 0, 256, 0, 1, 0, 1, 1.0f);

        // X += O @ proj_w + proj_b
        gemm_tc<false,0,true><<<dim3(8, 27, NBATCH), 256>>>(
            pY, SX, 0, 1024,
            projw + (size_t)i*1024*1024, 0, 0, 1024,
            pX, SX, 0, 1024,
            projb + (size_t)i*1024, 1, 0, 1024, 1024, 1, 0, 0, 1.0f);

        ln_k<<<dim3(NMAXT, NBATCH), 256>>>(pX, pY, ln2w + i*1024, ln2b + i*1024);

        // H = gelu(Y @ mlp_w1 + mlp_b1)
        gemm_tc<false,1,false><<<dim3(32, 27, NBATCH), 256>>>(
            pY, SX, 0, 1024,
            m1w + (size_t)i*1024*4096, 0, 0, 4096,
            pH, SH, 0, 4096,
            m1b + (size_t)i*4096, 1, 0, 4096, 1024, 1, 0, 0, 1.0f);

        // X += H @ mlp_w2 + mlp_b2
        gemm_tc<false,0,true><<<dim3(8, 27, NBATCH), 256>>>(
            pH, SH, 0, 4096,
            m2w + (size_t)i*4096*1024, 0, 0, 1024,
            pX, SX, 0, 1024,
            m2b + (size_t)i*1024, 1, 0, 1024, 4096, 1, 0, 0, 1.0f);
    }

    out_k<<<dim3(1024, NBATCH), 256>>>(img, out);
}

// round 5
// speedup vs baseline: 1.3207x; 1.3207x over previous
#include <cuda_runtime.h>
#include <math.h>
#include <stdint.h>

#define NMAXT 3329      // 1024 query + 1 sep + 2304 max prompts (logical)
#define NPAD  3344      // token-dim padding (multiple of 16)
#define SLD   3344      // score-matrix row stride
#define GPTS  2304
#define NBATCH 4

// ---------------- static device scratch (zero-initialized, never freed) ---------
__device__ int   g_M[NBATCH];
__device__ int   g_rows[NBATCH*GPTS];
__device__ int   g_cols[NBATCH*GPTS];
__device__ float g_X   [(size_t)NBATCH*NPAD*1024];
__device__ float g_Y   [(size_t)NBATCH*NPAD*1024];
__device__ float g_QKV [(size_t)NBATCH*NPAD*3072];   // pad rows stay 0 (V zeros)
__device__ float g_S   [(size_t)NBATCH*4*NPAD*SLD];  // pad cols stay 0
__device__ float g_Hbuf[(size_t)NBATCH*NPAD*4096];
__device__ float g_Qpe [1024*1024];
__device__ float g_Ppe [(size_t)NBATCH*GPTS*1024];
__device__ float g_Hp  [(size_t)NBATCH*GPTS*512];
__device__ float g_Pft [(size_t)NBATCH*GPTS*1024];

__device__ __forceinline__ float geluf(float x) {
    return 0.5f * x * (1.0f + erff(x * 0.7071067811865475f));
}
__device__ __forceinline__ float tf32r(float x) {
    float r; asm("cvt.rna.tf32.f32 %0, %1;" : "=f"(r) : "f"(x)); return r;
}
__device__ __forceinline__ float warpSum(float v) {
    #pragma unroll
    for (int o = 16; o; o >>= 1) v += __shfl_xor_sync(0xFFFFFFFFu, v, o);
    return v;
}
__device__ __forceinline__ float warpMax(float v) {
    #pragma unroll
    for (int o = 16; o; o >>= 1) v = fmaxf(v, __shfl_xor_sync(0xFFFFFFFFu, v, o));
    return v;
}

// ---------------- mask compaction (row-major order == np.nonzero) ---------------
__global__ void compact_k(const int* __restrict__ mask) {
    int b = threadIdx.x;
    if (b >= NBATCH) return;
    const int* mb = mask + b * GPTS;
    int cnt = 0;
    for (int i = 0; i < GPTS; i++) {
        if (mb[i] > 0) {
            g_rows[b*GPTS + cnt] = i / 48;
            g_cols[b*GPTS + cnt] = i % 48;
            cnt++;
        }
    }
    g_M[b] = cnt;
}

// ---------------- query positional encoding -------------------------------------
__global__ void qpe_k(const float* __restrict__ gauss) {
    int t = blockIdx.x;            // t = i*32 + j
    int i = t >> 5, j = t & 31;
    float cx = 2.0f * ((j + 0.5f) / 32.0f) - 1.0f;
    float cy = 2.0f * ((i + 0.5f) / 32.0f) - 1.0f;
    for (int k = threadIdx.x; k < 512; k += 256) {
        float ang = 6.283185307179586f * (cx * gauss[k] + cy * gauss[512 + k]);
        g_Qpe[(size_t)t*1024 + k]       = sinf(ang);
        g_Qpe[(size_t)t*1024 + 512 + k] = cosf(ang);
    }
}

// ------------- prompt PE + depth hidden layer gelu(d*w1+b1) ---------------------
__global__ void pembed_k(const float* __restrict__ depth, const float* __restrict__ gauss,
                         const float* __restrict__ w1, const float* __restrict__ b1) {
    int b = blockIdx.y, j = blockIdx.x;
    if (j >= g_M[b]) return;
    int r = g_rows[b*GPTS + j], c = g_cols[b*GPTS + j];
    float cx = 2.0f * ((c + 0.5f) / 48.0f) - 1.0f;
    float cy = 2.0f * ((r + 0.5f) / 48.0f) - 1.0f;
    float d = depth[b*GPTS + r*48 + c];
    size_t base = (size_t)b*GPTS + j;
    for (int k = threadIdx.x; k < 512; k += 256) {
        float ang = 6.283185307179586f * (cx * gauss[k] + cy * gauss[512 + k]);
        g_Ppe[base*1024 + k]       = sinf(ang);
        g_Ppe[base*1024 + 512 + k] = cosf(ang);
        g_Hp [base*512  + k]       = geluf(fmaf(d, w1[k], b1[k]));
    }
}

// ---------------- build residual stream -----------------------------------------
__global__ void build_x(const float* __restrict__ img, const float* __restrict__ sep0) {
    int b = blockIdx.y, t = blockIdx.x;
    if (t >= 1025 + g_M[b]) return;
    float* x = g_X + ((size_t)b*NPAD + t) * 1024;
    if (t < 1024) {
        const float* im = img + ((size_t)b*1024 + t) * 1024;
        for (int c = threadIdx.x; c < 1024; c += 256) x[c] = im[c] + g_Qpe[(size_t)t*1024 + c];
    } else if (t == 1024) {
        for (int c = threadIdx.x; c < 1024; c += 256) x[c] = sep0[c];
    } else {
        size_t base = (size_t)b*GPTS + (t - 1025);
        for (int c = threadIdx.x; c < 1024; c += 256)
            x[c] = g_Pft[base*1024 + c] + g_Ppe[base*1024 + c];
    }
}

__global__ void sep_rep(const float* __restrict__ sep1) {
    int b = blockIdx.x;
    float* x = g_X + ((size_t)b*NPAD + 1024) * 1024;
    for (int c = threadIdx.x; c < 1024; c += blockDim.x) x[c] = sep1[c];
}

// ---------------- layernorm -----------------------------------------------------
__global__ void ln_k(const float* __restrict__ Xin, float* __restrict__ Yout,
                     const float* __restrict__ w, const float* __restrict__ bb) {
    int b = blockIdx.y, t = blockIdx.x;
    if (t >= 1025 + g_M[b]) return;
    int tid = threadIdx.x;
    const float4* x4 = (const float4*)(Xin + ((size_t)b*NPAD + t) * 1024);
    float4 v = x4[tid];
    float s  = v.x + v.y + v.z + v.w;
    float sq = v.x*v.x + v.y*v.y + v.z*v.z + v.w*v.w;
    __shared__ float shs[8], shq[8], res[2];
    float ws = warpSum(s), wq = warpSum(sq);
    if ((tid & 31) == 0) { shs[tid>>5] = ws; shq[tid>>5] = wq; }
    __syncthreads();
    if (tid == 0) {
        float a = 0.f, q = 0.f;
        #pragma unroll
        for (int i = 0; i < 8; i++) { a += shs[i]; q += shq[i]; }
        res[0] = a; res[1] = q;
    }
    __syncthreads();
    float mean = res[0] * (1.0f/1024.0f);
    float var  = res[1] * (1.0f/1024.0f) - mean*mean;
    float rstd = rsqrtf(var + 1e-5f);
    float4 wv = ((const float4*)w)[tid];
    float4 bv = ((const float4*)bb)[tid];
    float4 o;
    o.x = (v.x - mean) * rstd * wv.x + bv.x;
    o.y = (v.y - mean) * rstd * wv.y + bv.y;
    o.z = (v.z - mean) * rstd * wv.z + bv.z;
    o.w = (v.w - mean) * rstd * wv.w + bv.w;
    ((float4*)(Yout + ((size_t)b*NPAD + t) * 1024))[tid] = o;
}

// ---------------- fused single-pass row softmax (regs hold the row) -------------
__global__ void softmax_k() {
    int z = blockIdx.y;            // b*4 + head
    int b = z >> 2;
    int Nd = 1025 + g_M[b];
    int row = blockIdx.x;
    if (row >= Nd) return;
    float* s = g_S + (size_t)z*NPAD*SLD + (size_t)row*SLD;
    int tid = threadIdx.x;
    __shared__ float red[8];

    float vals[14];
    float m = -3.4e38f;
    #pragma unroll
    for (int t = 0; t < 14; t++) {
        int j = tid + t*256;
        if (j < Nd) { vals[t] = s[j]; m = fmaxf(m, vals[t]); }
    }
    m = warpMax(m);
    if ((tid & 31) == 0) red[tid>>5] = m;
    __syncthreads();
    if (tid == 0) {
        float v = red[0];
        #pragma unroll
        for (int i = 1; i < 8; i++) v = fmaxf(v, red[i]);
        red[0] = v;
    }
    __syncthreads();
    m = red[0];
    __syncthreads();

    float sum = 0.f;
    #pragma unroll
    for (int t = 0; t < 14; t++) {
        int j = tid + t*256;
        if (j < Nd) { vals[t] = expf(vals[t] - m); sum += vals[t]; }
    }
    sum = warpSum(sum);
    if ((tid & 31) == 0) red[tid>>5] = sum;
    __syncthreads();
    if (tid == 0) {
        float v = 0.f;
        #pragma unroll
        for (int i = 0; i < 8; i++) v += red[i];
        red[0] = v;
    }
    __syncthreads();
    float inv = 1.0f / red[0];
    #pragma unroll
    for (int t = 0; t < 14; t++) {
        int j = tid + t*256;
        if (j < Nd) s[j] = vals[t] * inv;
    }
}

// =========================== tf32 tensor-core GEMM ==============================
// C = alpha * A @ (TRANSB ? B^T : B) (+bias)(+gelu)(+=C)
// 128x128x16 CTA tile, 8 warps (2x4), 64x32 warp tile, m16n8k8 tf32 mma,
// 2-stage cp.async double-buffered mainloop.
__device__ __forceinline__ int dimval(int st, int dyn, int b) {
    if (dyn == 1) return 1025 + g_M[b];
    if (dyn == 2) return g_M[b];
    return st;
}

__device__ __forceinline__ void cpa16(uint32_t dst, const void* src, int srcBytes) {
    asm volatile("cp.async.cg.shared.global [%0], [%1], 16, %2;"
                 :: "r"(dst), "l"(src), "r"(srcBytes));
}

#define MMA_TF32(d, a, bq)                                              \
    asm volatile("mma.sync.aligned.m16n8k8.row.col.f32.tf32.tf32.f32 "  \
        "{%0,%1,%2,%3},{%4,%5,%6,%7},{%8,%9},{%0,%1,%2,%3};"            \
        : "+f"(d[0]),"+f"(d[1]),"+f"(d[2]),"+f"(d[3])                   \
        : "r"(a[0]),"r"(a[1]),"r"(a[2]),"r"(a[3]),"r"(bq[0]),"r"(bq[1]))

template<bool TRANSB, int EPI, bool ACCUM>
__global__ void __launch_bounds__(256) gemm_tc(
    const float* __restrict__ A, long long aOut, long long aIn, int lda,
    const float* __restrict__ B, long long bOut, long long bIn, int ldb,
    float* __restrict__ C, long long cOut, long long cIn, int ldc,
    const float* __restrict__ bias,
    int nInner, int Mst, int Nst, int Kst,
    int dynM, int dynN, int dynK, float alpha)
{
    int z = blockIdx.z;
    int b = z / nInner, ii = z - b*nInner;
    int Mr = dimval(Mst, dynM, b);
    int Nc = dimval(Nst, dynN, b);
    int K  = dimval(Kst, dynK, b);
    int Kpad = (K + 15) & ~15;          // padding regions hold zeros by construction
    int m0 = blockIdx.y * 128, n0 = blockIdx.x * 128;
    if (m0 >= Mr || n0 >= Nc) return;
    A += b*aOut + ii*aIn;
    B += b*bOut + ii*bIn;
    C += b*cOut + ii*cIn;

    // A tiles: [m(128)][k(16)] pad->20.  B tiles:
    //   TRANSB : [n(128)][k(16)] pad->20 (2560 floats)
    //   !TRANSB: [k(16)][n(128)] pad->136 (2176 floats)
    __shared__ __align__(16) float Asm[2*2560];
    __shared__ __align__(16) float Bsm[2*2560];
    uint32_t sA = (uint32_t)__cvta_generic_to_shared(Asm);
    uint32_t sB = (uint32_t)__cvta_generic_to_shared(Bsm);

    int tid  = threadIdx.x;
    int wid  = tid >> 5, lane = tid & 31;
    int wm   = (wid >> 2) * 64;
    int wn   = (wid & 3) * 32;
    int g    = lane >> 2, t4 = lane & 3;

    float acc[4][4][4];
    #pragma unroll
    for (int i = 0; i < 4; i++)
        #pragma unroll
        for (int j = 0; j < 4; j++)
            #pragma unroll
            for (int e = 0; e < 4; e++) acc[i][j][e] = 0.f;

    auto issue = [&](int kt, int buf) {
        int k0 = kt << 4;
        // A tile: 128x16 -> 512 x 16B, 2 per thread
        #pragma unroll
        for (int i = 0; i < 2; i++) {
            int idx = tid + 256*i;
            int r = idx >> 2, c4 = (idx & 3) << 2;
            int gm = m0 + r;
            bool ok = gm < Mr;
            const float* src = ok ? (A + (long long)gm*lda + k0 + c4) : A;
            cpa16(sA + (uint32_t)(buf*2560 + r*20 + c4)*4, src, ok ? 16 : 0);
        }
        if (TRANSB) {
            #pragma unroll
            for (int i = 0; i < 2; i++) {
                int idx = tid + 256*i;
                int r = idx >> 2, c4 = (idx & 3) << 2;    // r = n, c4 = k
                int gn = n0 + r;
                bool ok = gn < Nc;
                const float* src = ok ? (B + (long long)gn*ldb + k0 + c4) : B;
                cpa16(sB + (uint32_t)(buf*2560 + r*20 + c4)*4, src, ok ? 16 : 0);
            }
        } else {
            // N always static multiple of 128 here; K rows always in-allocation.
            #pragma unroll
            for (int i = 0; i < 2; i++) {
                int idx = tid + 256*i;
                int r = idx >> 5, c4 = (idx & 31) << 2;   // r = k, c4 = n
                const float* src = B + (long long)(k0 + r)*ldb + n0 + c4;
                cpa16(sB + (uint32_t)(buf*2560 + r*136 + c4)*4, src, 16);
            }
        }
    };

    auto compute = [&](int buf) {
        const float* Ab = Asm + buf*2560;
        const float* Bb = Bsm + buf*2560;
        #pragma unroll
        for (int ks = 0; ks < 2; ks++) {
            int kk = ks * 8;
            uint32_t af[4][4], bf[4][2];
            #pragma unroll
            for (int mf = 0; mf < 4; mf++) {
                int r = wm + mf*16;
                af[mf][0] = __float_as_uint(tf32r(Ab[(r+g  )*20 + kk+t4  ]));
                af[mf][1] = __float_as_uint(tf32r(Ab[(r+g+8)*20 + kk+t4  ]));
                af[mf][2] = __float_as_uint(tf32r(Ab[(r+g  )*20 + kk+t4+4]));
                af[mf][3] = __float_as_uint(tf32r(Ab[(r+g+8)*20 + kk+t4+4]));
            }
            #pragma unroll
            for (int nf = 0; nf < 4; nf++) {
                int c = wn + nf*8 + g;
                if (TRANSB) {
                    bf[nf][0] = __float_as_uint(tf32r(Bb[c*20 + kk+t4  ]));
                    bf[nf][1] = __float_as_uint(tf32r(Bb[c*20 + kk+t4+4]));
                } else {
                    bf[nf][0] = __float_as_uint(tf32r(Bb[(kk+t4  )*136 + c]));
                    bf[nf][1] = __float_as_uint(tf32r(Bb[(kk+t4+4)*136 + c]));
                }
            }
            #pragma unroll
            for (int mf = 0; mf < 4; mf++)
                #pragma unroll
                for (int nf = 0; nf < 4; nf++)
                    MMA_TF32(acc[mf][nf], af[mf], bf[nf]);
        }
    };

    int ntiles = Kpad >> 4;
    issue(0, 0);
    asm volatile("cp.async.commit_group;" ::: "memory");
    for (int it = 0; it < ntiles; it++) {
        if (it + 1 < ntiles) issue(it + 1, (it + 1) & 1);
        asm volatile("cp.async.commit_group;" ::: "memory");
        asm volatile("cp.async.wait_group 1;" ::: "memory");
        __syncthreads();
        compute(it & 1);
        __syncthreads();
    }

    // ---- epilogue ----
    #pragma unroll
    for (int mf = 0; mf < 4; mf++) {
        #pragma unroll
        for (int nf = 0; nf < 4; nf++) {
            int gmA = m0 + wm + mf*16 + g;
            int gnA = n0 + wn + nf*8 + 2*t4;
            #pragma unroll
            for (int e = 0; e < 4; e++) {
                int gm = gmA + ((e >> 1) << 3);
                int gn = gnA + (e & 1);
                if (gm < Mr && gn < Nc) {
                    float v = acc[mf][nf][e] * alpha;
                    if (bias) v += bias[gn];
                    if (EPI == 1) v = geluf(v);
                    long long off = (long long)gm*ldc + gn;
                    if (ACCUM) C[off] += v;
                    else       C[off]  = v;
                }
            }
        }
    }
}

// ---------------- output ---------------------------------------------------------
__global__ void out_k(const float* __restrict__ img, float* __restrict__ out) {
    int b = blockIdx.y, t = blockIdx.x;
    const float* src = (g_M[b] == 0)
        ? img + ((size_t)b*1024 + t) * 1024
        : g_X + ((size_t)b*NPAD + t) * 1024;
    float* o = out + ((size_t)b*1024 + t) * 1024;
    for (int c = threadIdx.x; c < 1024; c += 256) o[c] = src[c];
}

// ================================ host ==========================================
extern "C" void kernel_launch(void* const* d_in, const int* in_sizes, int n_in,
                              void* d_out, int out_size) {
    const float* img   = (const float*)d_in[0];
    const float* depth = (const float*)d_in[1];
    const int*   mask  = (const int*)  d_in[2];
    const float* gauss = (const float*)d_in[5];
    const float* w1    = (const float*)d_in[6];
    const float* b1    = (const float*)d_in[7];
    const float* w2    = (const float*)d_in[8];
    const float* b2    = (const float*)d_in[9];
    const float* sep   = (const float*)d_in[10];
    const float* ln1w  = (const float*)d_in[11];
    const float* ln1b  = (const float*)d_in[12];
    const float* qkvw  = (const float*)d_in[13];
    const float* qkvb  = (const float*)d_in[14];
    const float* projw = (const float*)d_in[15];
    const float* projb = (const float*)d_in[16];
    const float* ln2w  = (const float*)d_in[17];
    const float* ln2b  = (const float*)d_in[18];
    const float* m1w   = (const float*)d_in[19];
    const float* m1b   = (const float*)d_in[20];
    const float* m2w   = (const float*)d_in[21];
    const float* m2b   = (const float*)d_in[22];
    float* out = (float*)d_out;

    float *pX, *pY, *pQKV, *pS, *pH, *pHp, *pPft;
    cudaGetSymbolAddress((void**)&pX,   g_X);
    cudaGetSymbolAddress((void**)&pY,   g_Y);
    cudaGetSymbolAddress((void**)&pQKV, g_QKV);
    cudaGetSymbolAddress((void**)&pS,   g_S);
    cudaGetSymbolAddress((void**)&pH,   g_Hbuf);
    cudaGetSymbolAddress((void**)&pHp,  g_Hp);
    cudaGetSymbolAddress((void**)&pPft, g_Pft);

    const long long SX   = (long long)NPAD * 1024;
    const long long SQKV = (long long)NPAD * 3072;
    const long long SH   = (long long)NPAD * 4096;
    const long long SS1  = (long long)NPAD * SLD;    // per head
    const long long SSB  = 4LL * SS1;                // per batch

    compact_k<<<1, NBATCH>>>(mask);
    qpe_k<<<1024, 256>>>(gauss);
    pembed_k<<<dim3(GPTS, NBATCH), 256>>>(depth, gauss, w1, b1);

    // prompt features: Pft = Hp @ w2 + b2   (rows = g_M[b])
    gemm_tc<false,0,false><<<dim3(8, 18, NBATCH), 256>>>(
        pHp, (long long)GPTS*512, 0, 512,
        w2, 0, 0, 1024,
        pPft, (long long)GPTS*1024, 0, 1024,
        b2, 1, 0, 1024, 512, 2, 0, 0, 1.0f);

    build_x<<<dim3(NMAXT, NBATCH), 256>>>(img, sep);

    for (int i = 0; i < 2; i++) {
        if (i) sep_rep<<<NBATCH, 256>>>(sep + (size_t)i*1024);

        ln_k<<<dim3(NMAXT, NBATCH), 256>>>(pX, pY, ln1w + i*1024, ln1b + i*1024);

        // QKV = Y @ qkv_w + qkv_b
        gemm_tc<false,0,false><<<dim3(24, 27, NBATCH), 256>>>(
            pY, SX, 0, 1024,
            qkvw + (size_t)i*1024*3072, 0, 0, 3072,
            pQKV, SQKV, 0, 3072,
            qkvb + (size_t)i*3072, 1, 0, 3072, 1024, 1, 0, 0, 1.0f);

        // S = Q K^T / 16   (per head, z = b*4+h)
        gemm_tc<true,0,false><<<dim3(27, 27, NBATCH*4), 256>>>(
            pQKV, SQKV, 256, 3072,
            pQKV + 1024, SQKV, 256, 3072,
            pS, SSB, SS1, SLD,
            nullptr, 4, 0, 0, 256, 1, 1, 0, 0.0625f);

        softmax_k<<<dim3(NMAXT, NBATCH*4), 256>>>();

        // O = S @ V  -> Y (per-head column slice)
        gemm_tc<false,0,false><<<dim3(2, 27, NBATCH*4), 256>>>(
            pS, SSB, SS1, SLD,
            pQKV + 2048, SQKV, 256, 3072,
            pY, SX, 256, 1024,
            nullptr, 4, 0, 256, 0, 1, 0, 1, 1.0f);

        // X += O @ proj_w + proj_b
        gemm_tc<false,0,true><<<dim3(8, 27, NBATCH), 256>>>(
            pY, SX, 0, 1024,
            projw + (size_t)i*1024*1024, 0, 0, 1024,
            pX, SX, 0, 1024,
            projb + (size_t)i*1024, 1, 0, 1024, 1024, 1, 0, 0, 1.0f);

        ln_k<<<dim3(NMAXT, NBATCH), 256>>>(pX, pY, ln2w + i*1024, ln2b + i*1024);

        // H = gelu(Y @ mlp_w1 + mlp_b1)
        gemm_tc<false,1,false><<<dim3(32, 27, NBATCH), 256>>>(
            pY, SX, 0, 1024,
            m1w + (size_t)i*1024*4096, 0, 0, 4096,
            pH, SH, 0, 4096,
            m1b + (size_t)i*4096, 1, 0, 4096, 1024, 1, 0, 0, 1.0f);

        // X += H @ mlp_w2 + mlp_b2
        gemm_tc<false,0,true><<<dim3(8, 27, NBATCH), 256>>>(
            pH, SH, 0, 4096,
            m2w + (size_t)i*4096*1024, 0, 0, 1024,
            pX, SX, 0, 1024,
            m2b + (size_t)i*1024, 1, 0, 1024, 4096, 1, 0, 0, 1.0f);
    }

    out_k<<<dim3(1024, NBATCH), 256>>>(img, out);
}